// round 4
// baseline (speedup 1.0000x reference)
#include <cuda_runtime.h>
#include <cuda_bf16.h>
#include <cstdint>

#define LL 512
#define DD 128

// ---------------- scratch globals ----------------
__device__ float g_keep[LL];
__device__ float g_seq[LL * DD];
__device__ float g_Q[LL * DD];
__device__ float g_qp[LL * DD];
__device__ float g_kp[LL * DD];
__device__ float g_vp[LL * DD];
__device__ float g_x[LL * DD];
__device__ float g_h[LL * DD];
__device__ float g_twlog[2 * LL * LL];
__device__ __nv_bfloat16 g_Bimg[2 * 128 * 128];  // [s][n][k] = Wt[s][k][n]

__device__ __forceinline__ uint32_t smem_to_u32(const void* p) {
    uint32_t a;
    asm("{ .reg .u64 t; cvta.to.shared.u64 t, %1; cvt.u32.u64 %0, t; }" : "=r"(a) : "l"(p));
    return a;
}

__device__ __forceinline__ void ldmatrix_x4(uint32_t* r, uint32_t addr) {
    asm volatile("ldmatrix.sync.aligned.m8n8.x4.shared.b16 {%0,%1,%2,%3}, [%4];"
                 : "=r"(r[0]), "=r"(r[1]), "=r"(r[2]), "=r"(r[3]) : "r"(addr));
}
__device__ __forceinline__ void ldmatrix_x2(uint32_t& r0, uint32_t& r1, uint32_t addr) {
    asm volatile("ldmatrix.sync.aligned.m8n8.x2.shared.b16 {%0,%1}, [%2];"
                 : "=r"(r0), "=r"(r1) : "r"(addr));
}
__device__ __forceinline__ void mma16816(float* c, const uint32_t* a, uint32_t b0, uint32_t b1) {
    asm volatile(
        "mma.sync.aligned.m16n8k16.row.col.f32.bf16.bf16.f32 "
        "{%0,%1,%2,%3}, {%4,%5,%6,%7}, {%8,%9}, {%0,%1,%2,%3};"
        : "+f"(c[0]), "+f"(c[1]), "+f"(c[2]), "+f"(c[3])
        : "r"(a[0]), "r"(a[1]), "r"(a[2]), "r"(a[3]), "r"(b0), "r"(b1));
}

// ---------------- prep: keep + masked seqs ----------------
__global__ void prep_kernel(const int* __restrict__ logs, const float* __restrict__ seqs) {
    int i = blockIdx.x * 256 + threadIdx.x;  // 65536
    if (i < LL) g_keep[i] = (logs[i] == 0) ? 0.0f : 1.0f;
    int row = i >> 7;
    float k = (logs[row] == 0) ? 0.0f : 1.0f;
    g_seq[i] = seqs[i] * k;
}

// ---------------- B images: g_Bimg[s][n][k] = bf16(Wt[s][k][n]) ----------------
__global__ void bimg_kernel(const float* __restrict__ Wt) {
    int id = blockIdx.x * 256 + threadIdx.x;  // 32768
    int s = id >> 14, e = id & 16383;
    int n = e >> 7, k = e & 127;
    g_Bimg[id] = __float2bfloat16(Wt[s * 16384 + k * 128 + n]);
}

// ---------------- big fused time-bias kernel (HMMA mma.sync) ----------------
// smem: A tile 128 rows x 272B, B images 2 x 128 rows x 272B, scalars
#define TW_SA   0
#define TW_SB   34816
#define TW_SSC  (TW_SB + 2 * 34816)      // 104448
#define TW_SMEM (TW_SSC + 2064)          // 106512

__global__ void __launch_bounds__(256, 2)
twbias_kernel(const float* __restrict__ T, const float* __restrict__ bt,
              const float* __restrict__ Wtp, const float* __restrict__ btp) {
    extern __shared__ char smem[];
    uint32_t sb = smem_to_u32(smem);
    int tid = threadIdx.x;
    float* sc = (float*)(smem + TW_SSC);

    // stage B images (linear copy, padded rows)
    {
        const uint4* src = (const uint4*)g_Bimg;  // 4096 uint4 = 8 bf16 each
        for (int i = tid; i < 4096; i += 256) {
            int e = i * 8;                         // element index
            int s = e >> 14, n = (e >> 7) & 127, k = e & 127;
            *(uint4*)(smem + TW_SB + s * 34816 + n * 272 + k * 2) = src[i];
        }
    }
    if (tid < 128) {
        sc[tid]       = bt[tid];
        sc[128 + tid] = bt[128 + tid];
        sc[256 + tid] = Wtp[tid];
        sc[384 + tid] = Wtp[128 + tid];
    }
    if (tid == 0) { sc[512] = btp[0]; sc[513] = btp[1]; }

    // load + convert A tile: 128 rows x 128 fp32 -> bf16, padded stride 272B
    {
        size_t r0 = (size_t)blockIdx.x * 128;
        const float4* Tb = (const float4*)(T + r0 * 128);
#pragma unroll
        for (int i = 0; i < 16; i++) {
            int c = tid + 256 * i;                 // 4096 float4 chunks
            int r = c >> 5, kc = (c & 31) << 2;
            float4 a = Tb[c];
            __nv_bfloat162 lo = __floats2bfloat162_rn(a.x, a.y);
            __nv_bfloat162 hi = __floats2bfloat162_rn(a.z, a.w);
            uint2 u;
            u.x = *reinterpret_cast<uint32_t*>(&lo);
            u.y = *reinterpret_cast<uint32_t*>(&hi);
            *(uint2*)(smem + TW_SA + r * 272 + kc * 2) = u;
        }
    }
    __syncthreads();

    int lane = tid & 31, w = tid >> 5;
    int s = w >> 2, mrow0 = (w & 3) * 32;

    // A fragment lane geometry (ldmatrix x4)
    int l8 = lane & 7, gq = lane >> 3;
    int arow = (gq & 1) * 8 + l8;
    int akoff = (gq >> 1) * 8;

    uint32_t a[2][8][4];
#pragma unroll
    for (int mt = 0; mt < 2; mt++)
#pragma unroll
        for (int kt = 0; kt < 8; kt++) {
            uint32_t addr = sb + TW_SA + (uint32_t)(mrow0 + mt * 16 + arow) * 272
                          + (uint32_t)(kt * 16 + akoff) * 2;
            ldmatrix_x4(a[mt][kt], addr);
        }

    // B fragment lane geometry (ldmatrix x2; lanes 0-15 meaningful)
    int bg = (lane >> 3) & 1;
    uint32_t b_base = sb + TW_SB + (uint32_t)s * 34816;

    float accR[2][2] = {{0.f, 0.f}, {0.f, 0.f}};
#pragma unroll
    for (int nt = 0; nt < 16; nt++) {
        float c0[4] = {0.f, 0.f, 0.f, 0.f};
        float c1[4] = {0.f, 0.f, 0.f, 0.f};
#pragma unroll
        for (int kt = 0; kt < 8; kt++) {
            uint32_t baddr = b_base + (uint32_t)(nt * 8 + l8) * 272
                           + (uint32_t)(kt * 16 + bg * 8) * 2;
            uint32_t b0, b1;
            ldmatrix_x2(b0, b1, baddr);
            mma16816(c0, a[0][kt], b0, b1);
            mma16816(c1, a[1][kt], b0, b1);
        }
        int q = lane & 3;
        int n0 = nt * 8 + 2 * q;
        float bt0 = sc[s * 128 + n0],       bt1 = sc[s * 128 + n0 + 1];
        float wp0 = sc[256 + s * 128 + n0], wp1 = sc[256 + s * 128 + n0 + 1];
        accR[0][0] += fmaxf(c0[0] + bt0, 0.f) * wp0 + fmaxf(c0[1] + bt1, 0.f) * wp1;
        accR[0][1] += fmaxf(c0[2] + bt0, 0.f) * wp0 + fmaxf(c0[3] + bt1, 0.f) * wp1;
        accR[1][0] += fmaxf(c1[0] + bt0, 0.f) * wp0 + fmaxf(c1[1] + bt1, 0.f) * wp1;
        accR[1][1] += fmaxf(c1[2] + bt0, 0.f) * wp0 + fmaxf(c1[3] + bt1, 0.f) * wp1;
    }
    // reduce over the quad (lanes differing in bits 0,1 share a row)
#pragma unroll
    for (int o = 1; o <= 2; o <<= 1) {
        accR[0][0] += __shfl_xor_sync(0xffffffffu, accR[0][0], o);
        accR[0][1] += __shfl_xor_sync(0xffffffffu, accR[0][1], o);
        accR[1][0] += __shfl_xor_sync(0xffffffffu, accR[1][0], o);
        accR[1][1] += __shfl_xor_sync(0xffffffffu, accR[1][1], o);
    }
    if ((lane & 3) == 0) {
        int g = lane >> 2;
        float bp = sc[512 + s];
#pragma unroll
        for (int mt = 0; mt < 2; mt++)
#pragma unroll
            for (int hh = 0; hh < 2; hh++) {
                int row = mrow0 + mt * 16 + hh * 8 + g;
                size_t p = (size_t)blockIdx.x * 128 + (size_t)row;
                float tp = accR[mt][hh] + bp;
                float lg = (tp >= 0.f) ? -log1pf(expf(-tp)) : tp - log1pf(expf(tp));
                g_twlog[(size_t)s * (LL * LL) + p] = lg;
            }
    }
}

// ---------------- LayerNorm: one row per block; mode 0->g_Q, 1->g_x, 2->outp ----
__global__ void ln_kernel(int mode, const float* __restrict__ g,
                          const float* __restrict__ b, float* __restrict__ outp) {
    int row = blockIdx.x, tid = threadIdx.x;
    float* out = (mode == 0) ? g_Q : (mode == 1) ? g_x : outp;
    float x = g_seq[row * DD + tid];
    float s = x, s2 = x * x;
#pragma unroll
    for (int o = 16; o; o >>= 1) {
        s  += __shfl_xor_sync(0xffffffffu, s, o);
        s2 += __shfl_xor_sync(0xffffffffu, s2, o);
    }
    __shared__ float sh[8];
    if ((tid & 31) == 0) { sh[tid >> 5] = s; sh[4 + (tid >> 5)] = s2; }
    __syncthreads();
    s  = sh[0] + sh[1] + sh[2] + sh[3];
    s2 = sh[4] + sh[5] + sh[6] + sh[7];
    float m = s * (1.0f / DD);
    float v = s2 * (1.0f / DD) - m * m;
    float r = rsqrtf(v + 1e-8f);
    out[row * DD + tid] = (x - m) * r * g[tid] + b[tid];
}

// ---------------- QKV: grid (16, 4, 3) ----------------
__global__ void qkv_kernel(const float* __restrict__ Wq, const float* __restrict__ bq,
                           const float* __restrict__ Wk, const float* __restrict__ bk,
                           const float* __restrict__ Wv, const float* __restrict__ bv) {
    __shared__ float As[32 * 128];
    __shared__ float Ws[128 * 32];
    int z = blockIdx.z;
    const float* A    = (z == 0) ? g_Q : g_seq;
    const float* W    = (z == 0) ? Wq : (z == 1 ? Wk : Wv);
    const float* bias = (z == 0) ? bq : (z == 1 ? bk : bv);
    float* C          = (z == 0) ? g_qp : (z == 1 ? g_kp : g_vp);
    int r0 = blockIdx.x * 32, c0 = blockIdx.y * 32, tid = threadIdx.x;
    for (int i = tid; i < 32 * 128; i += 256) As[i] = A[(r0 + (i >> 7)) * 128 + (i & 127)];
    for (int i = tid; i < 128 * 32; i += 256) Ws[i] = W[(i >> 5) * 128 + c0 + (i & 31)];
    __syncthreads();
    int col = tid & 31, rg = tid >> 5;
    float acc[4] = {0, 0, 0, 0};
    for (int k = 0; k < 128; k++) {
        float w = Ws[k * 32 + col];
#pragma unroll
        for (int i = 0; i < 4; i++) acc[i] += As[(rg * 4 + i) * 128 + k] * w;
    }
    float b = bias[c0 + col];
#pragma unroll
    for (int i = 0; i < 4; i++) C[(r0 + rg * 4 + i) * 128 + c0 + col] = acc[i] + b;
}

// ---------------- FFN GEMM. mode1: relu(g_x@W1+b1)->g_h ; mode2: (g_x + g_h@W2+b2)*keep -> g_seq
__global__ void gemm_kernel(const float* __restrict__ W, const float* __restrict__ bias, int mode) {
    __shared__ float As[32 * 128];
    __shared__ float Ws[128 * 32];
    const float* A = (mode == 1) ? g_x : g_h;
    float* C       = (mode == 1) ? g_h : g_seq;
    int r0 = blockIdx.x * 32, c0 = blockIdx.y * 32, tid = threadIdx.x;
    for (int i = tid; i < 32 * 128; i += 256) As[i] = A[(r0 + (i >> 7)) * 128 + (i & 127)];
    for (int i = tid; i < 128 * 32; i += 256) Ws[i] = W[(i >> 5) * 128 + c0 + (i & 31)];
    __syncthreads();
    int col = tid & 31, rg = tid >> 5;
    float acc[4] = {0, 0, 0, 0};
    for (int k = 0; k < 128; k++) {
        float w = Ws[k * 32 + col];
#pragma unroll
        for (int i = 0; i < 4; i++) acc[i] += As[(rg * 4 + i) * 128 + k] * w;
    }
    float b = bias[c0 + col];
#pragma unroll
    for (int i = 0; i < 4; i++) {
        int row = r0 + rg * 4 + i;
        float v = acc[i] + b;
        if (mode == 1) v = fmaxf(v, 0.0f);
        else v = (g_x[row * 128 + c0 + col] + v) * g_keep[row];
        C[row * 128 + c0 + col] = v;
    }
}

// ---------------- attention: grid (4, 64), 128 thr, 8 q-rows/CTA ----------------
#define AKS 0
#define AVS (512 * 33 * 4)
#define ASB (2 * 512 * 33 * 4)
#define AQV (ASB + 512 * 4)
#define APART (AQV + 32 * 4)
#define ARED (APART + 128 * 4)
#define SMEM_ATTN (ARED + 64)

__global__ void __launch_bounds__(128, 1)
attn_kernel(int s, float* __restrict__ wout) {
    extern __shared__ char smem[];
    float* ks   = (float*)(smem + AKS);
    float* vs   = (float*)(smem + AVS);
    float* sbuf = (float*)(smem + ASB);
    float* qv   = (float*)(smem + AQV);
    float* part = (float*)(smem + APART);
    float* red  = (float*)(smem + ARED);
    const float* twlog = g_twlog + (size_t)s * (LL * LL);
    int h = blockIdx.x, q0 = blockIdx.y * 8, tid = threadIdx.x;

    for (int i = tid; i < 512 * 32; i += 128) {
        int kk = i >> 5, d = i & 31;
        ks[kk * 33 + d] = g_kp[kk * 128 + h * 32 + d];
        vs[kk * 33 + d] = g_vp[kk * 128 + h * 32 + d];
    }
    __syncthreads();

    const float NEGV = -4294967295.0f;
    const float SCALE = 0.17677669529663689f;  // 1/sqrt(32)

    for (int qi = 0; qi < 8; qi++) {
        int q = q0 + qi;
        if (tid < 32) qv[tid] = g_qp[q * 128 + h * 32 + tid];
        __syncthreads();
        bool padq = (g_keep[q] == 0.0f);
        float lmax = -3.4e38f;
        float sv[4];
#pragma unroll
        for (int it = 0; it < 4; it++) {
            int kk = tid + 128 * it;
            float sva;
            if (padq || kk > q) sva = NEGV;
            else {
                float dot = 0.0f;
#pragma unroll
                for (int d = 0; d < 32; d++) dot += qv[d] * ks[kk * 33 + d];
                sva = (dot + twlog[q * 512 + kk]) * SCALE;
            }
            sv[it] = sva;
            lmax = fmaxf(lmax, sva);
        }
#pragma unroll
        for (int o = 16; o; o >>= 1) lmax = fmaxf(lmax, __shfl_xor_sync(0xffffffffu, lmax, o));
        if ((tid & 31) == 0) red[tid >> 5] = lmax;
        __syncthreads();
        float mx = fmaxf(fmaxf(red[0], red[1]), fmaxf(red[2], red[3]));
        float lsum = 0.0f;
#pragma unroll
        for (int it = 0; it < 4; it++) { float e = expf(sv[it] - mx); sv[it] = e; lsum += e; }
#pragma unroll
        for (int o = 16; o; o >>= 1) lsum += __shfl_xor_sync(0xffffffffu, lsum, o);
        if ((tid & 31) == 0) red[4 + (tid >> 5)] = lsum;
        __syncthreads();
        float inv = 1.0f / (red[4] + red[5] + red[6] + red[7]);
#pragma unroll
        for (int it = 0; it < 4; it++) {
            int kk = tid + 128 * it;
            float wv = sv[it] * inv;
            sbuf[kk] = wv;
            wout[(size_t)h * 262144 + (size_t)q * 512 + kk] = wv;
        }
        __syncthreads();
        {
            int g = tid >> 5, d = tid & 31;
            float p = 0.0f;
            for (int kk = g * 128; kk < g * 128 + 128; kk++) p += sbuf[kk] * vs[kk * 33 + d];
            part[g * 32 + d] = p;
        }
        __syncthreads();
        if (tid < 32) {
            float o = part[tid] + part[32 + tid] + part[64 + tid] + part[96 + tid];
            g_seq[q * 128 + h * 32 + tid] = g_Q[q * 128 + h * 32 + tid] + o;
        }
        __syncthreads();
    }
}

// ---------------- launch ----------------
extern "C" void kernel_launch(void* const* d_in, const int* in_sizes, int n_in,
                              void* d_out, int out_size) {
    const int*   logs = (const int*)d_in[0];
    const float* seqs = (const float*)d_in[1];
    const float* tmk  = (const float*)d_in[2];
    const float* Wq   = (const float*)d_in[3];
    const float* bq   = (const float*)d_in[4];
    const float* Wk   = (const float*)d_in[5];
    const float* bk   = (const float*)d_in[6];
    const float* Wv   = (const float*)d_in[7];
    const float* bv   = (const float*)d_in[8];
    const float* Wt   = (const float*)d_in[9];
    const float* bt   = (const float*)d_in[10];
    const float* Wtp  = (const float*)d_in[11];
    const float* btp  = (const float*)d_in[12];
    const float* ln1g = (const float*)d_in[13];
    const float* ln1b = (const float*)d_in[14];
    const float* ln2g = (const float*)d_in[15];
    const float* ln2b = (const float*)d_in[16];
    const float* W1   = (const float*)d_in[17];
    const float* b1   = (const float*)d_in[18];
    const float* W2   = (const float*)d_in[19];
    const float* b2   = (const float*)d_in[20];
    const float* lnfg = (const float*)d_in[21];
    const float* lnfb = (const float*)d_in[22];
    float* out = (float*)d_out;

    cudaFuncSetAttribute(twbias_kernel, cudaFuncAttributeMaxDynamicSharedMemorySize, TW_SMEM);
    cudaFuncSetAttribute(attn_kernel, cudaFuncAttributeMaxDynamicSharedMemorySize, SMEM_ATTN);

    prep_kernel<<<256, 256>>>(logs, seqs);
    bimg_kernel<<<128, 256>>>(Wt);
    twbias_kernel<<<2048, 256, TW_SMEM>>>(tmk, bt, Wtp, btp);

    for (int i = 0; i < 2; i++) {
        const int wo = i * 16384, bo = i * 128;
        ln_kernel<<<512, 128>>>(0, ln1g + bo, ln1b + bo, nullptr);
        qkv_kernel<<<dim3(16, 4, 3), 256>>>(Wq + wo, bq + bo, Wk + wo, bk + bo, Wv + wo, bv + bo);
        attn_kernel<<<dim3(4, 64), 128, SMEM_ATTN>>>(i, out + 65536 + (size_t)i * 1048576);
        ln_kernel<<<512, 128>>>(1, ln2g + bo, ln2b + bo, nullptr);
        gemm_kernel<<<dim3(16, 4), 256>>>(W1 + wo, b1 + bo, 1);
        gemm_kernel<<<dim3(16, 4), 256>>>(W2 + wo, b2 + bo, 2);
    }
    ln_kernel<<<512, 128>>>(2, lnfg, lnfb, out);
}

// round 6
// speedup vs baseline: 1.1283x; 1.1283x over previous
#include <cuda_runtime.h>
#include <cuda_bf16.h>
#include <cstdint>

#define LL 512
#define DD 128

// ---------------- scratch globals ----------------
__device__ float g_keep[LL];
__device__ float g_seq[LL * DD];
__device__ float g_Q[LL * DD];
__device__ float g_qp[LL * DD];
__device__ float g_kp[LL * DD];
__device__ float g_vp[LL * DD];
__device__ float g_x[LL * DD];
__device__ float g_h[LL * DD];
__device__ float g_twlog[2 * LL * LL];
__device__ __nv_bfloat16 g_Bimg[2 * 128 * 128];  // [s][n][k] = Wt[s][k][n]

__device__ __forceinline__ uint32_t smem_to_u32(const void* p) {
    uint32_t a;
    asm("{ .reg .u64 t; cvta.to.shared.u64 t, %1; cvt.u32.u64 %0, t; }" : "=r"(a) : "l"(p));
    return a;
}
__device__ __forceinline__ void ldmatrix_x4(uint32_t* r, uint32_t addr) {
    asm volatile("ldmatrix.sync.aligned.m8n8.x4.shared.b16 {%0,%1,%2,%3}, [%4];"
                 : "=r"(r[0]), "=r"(r[1]), "=r"(r[2]), "=r"(r[3]) : "r"(addr));
}
__device__ __forceinline__ void mma16816(float* c, const uint32_t* a, uint32_t b0, uint32_t b1) {
    asm volatile(
        "mma.sync.aligned.m16n8k16.row.col.f32.bf16.bf16.f32 "
        "{%0,%1,%2,%3}, {%4,%5,%6,%7}, {%8,%9}, {%0,%1,%2,%3};"
        : "+f"(c[0]), "+f"(c[1]), "+f"(c[2]), "+f"(c[3])
        : "r"(a[0]), "r"(a[1]), "r"(a[2]), "r"(a[3]), "r"(b0), "r"(b1));
}

// ---------------- prep ----------------
__global__ void prep_keep_kernel(const int* __restrict__ logs) {
    int i = threadIdx.x;  // 512
    g_keep[i] = (logs[i] == 0) ? 0.0f : 1.0f;
}
__global__ void prep_seq_kernel(const int* __restrict__ logs, const float* __restrict__ seqs) {
    int i = blockIdx.x * 256 + threadIdx.x;  // 65536
    int row = i >> 7;
    float k = (logs[row] == 0) ? 0.0f : 1.0f;
    g_seq[i] = seqs[i] * k;
}

// ---------------- B images: g_Bimg[s][n][k] = bf16(Wt[s][k][n]) ----------------
__global__ void bimg_kernel(const float* __restrict__ Wt) {
    int id = blockIdx.x * 256 + threadIdx.x;  // 32768
    int s = id >> 14, e = id & 16383;
    int n = e >> 7, k = e & 127;
    g_Bimg[id] = __float2bfloat16(Wt[s * 16384 + k * 128 + n]);
}

// ---------------- big fused time-bias kernel (HMMA mma.sync) ----------------
// smem: A tile 128 rows x 272B, B images 2 x 128 rows x 272B, scalars
#define TW_SA   0
#define TW_SB   34816
#define TW_SSC  (TW_SB + 2 * 34816)      // 104448
#define TW_SMEM (TW_SSC + 2064)          // 106512

__global__ void __launch_bounds__(256, 2)
twbias_kernel(const float* __restrict__ T, const float* __restrict__ bt,
              const float* __restrict__ Wtp, const float* __restrict__ btp) {
    extern __shared__ char smem[];
    uint32_t sb = smem_to_u32(smem);
    int tid = threadIdx.x;
    float* sc = (float*)(smem + TW_SSC);

    // stage B images (padded rows, 272B stride)
    {
        const uint4* src = (const uint4*)g_Bimg;  // 4096 uint4 = 8 bf16 each
        for (int i = tid; i < 4096; i += 256) {
            int e = i * 8;
            int s = e >> 14, n = (e >> 7) & 127, k = e & 127;
            *(uint4*)(smem + TW_SB + s * 34816 + n * 272 + k * 2) = src[i];
        }
    }
    if (tid < 128) {
        sc[tid]       = bt[tid];
        sc[128 + tid] = bt[128 + tid];
        sc[256 + tid] = Wtp[tid];
        sc[384 + tid] = Wtp[128 + tid];
    }
    if (tid == 0) { sc[512] = btp[0]; sc[513] = btp[1]; }

    // load + convert A tile: 128 rows x 128 fp32 -> bf16, stride 272B
    {
        size_t r0 = (size_t)blockIdx.x * 128;
        const float4* Tb = (const float4*)(T + r0 * 128);
#pragma unroll
        for (int i = 0; i < 16; i++) {
            int c = tid + 256 * i;
            int r = c >> 5, kc = (c & 31) << 2;
            float4 a = Tb[c];
            __nv_bfloat162 lo = __floats2bfloat162_rn(a.x, a.y);
            __nv_bfloat162 hi = __floats2bfloat162_rn(a.z, a.w);
            uint2 u;
            u.x = *reinterpret_cast<uint32_t*>(&lo);
            u.y = *reinterpret_cast<uint32_t*>(&hi);
            *(uint2*)(smem + TW_SA + r * 272 + kc * 2) = u;
        }
    }
    __syncthreads();

    int lane = tid & 31, w = tid >> 5;
    int s = w >> 2, mrow0 = (w & 3) * 32;

    int l8 = lane & 7, gq = lane >> 3;
    // A frag geometry (x4): groups -> (m0-7,k0-7),(m8-15,k0-7),(m0-7,k8-15),(m8-15,k8-15)
    int arow = (gq & 1) * 8 + l8;
    int akoff = (gq >> 1) * 8;

    uint32_t a[2][8][4];
#pragma unroll
    for (int mt = 0; mt < 2; mt++)
#pragma unroll
        for (int kt = 0; kt < 8; kt++) {
            uint32_t addr = sb + TW_SA + (uint32_t)(mrow0 + mt * 16 + arow) * 272
                          + (uint32_t)(kt * 16 + akoff) * 2;
            ldmatrix_x4(a[mt][kt], addr);
        }

    // B frag geometry (x4 over an nt-pair): groups -> (nt0,k0-7),(nt0,k8-15),(nt1,k0-7),(nt1,k8-15)
    int bntl = gq >> 1;              // which nt of the pair
    int bkoff = (gq & 1) * 8;
    uint32_t b_base = sb + TW_SB + (uint32_t)s * 34816;
    int qd = lane & 3;

    float accR[2][2] = {{0.f, 0.f}, {0.f, 0.f}};
#pragma unroll
    for (int ntp = 0; ntp < 8; ntp++) {
        float c[2][2][4];
#pragma unroll
        for (int i = 0; i < 2; i++)
#pragma unroll
            for (int j = 0; j < 2; j++)
#pragma unroll
                for (int t = 0; t < 4; t++) c[i][j][t] = 0.f;
#pragma unroll
        for (int kt = 0; kt < 8; kt++) {
            uint32_t baddr = b_base + (uint32_t)(ntp * 16 + bntl * 8 + l8) * 272
                           + (uint32_t)(kt * 16 + bkoff) * 2;
            uint32_t b[4];
            ldmatrix_x4(b, baddr);
            mma16816(c[0][0], a[0][kt], b[0], b[1]);
            mma16816(c[0][1], a[0][kt], b[2], b[3]);
            mma16816(c[1][0], a[1][kt], b[0], b[1]);
            mma16816(c[1][1], a[1][kt], b[2], b[3]);
        }
#pragma unroll
        for (int nh = 0; nh < 2; nh++) {
            int n0 = (ntp * 2 + nh) * 8 + 2 * qd;
            float bt0 = sc[s * 128 + n0],       bt1 = sc[s * 128 + n0 + 1];
            float wp0 = sc[256 + s * 128 + n0], wp1 = sc[256 + s * 128 + n0 + 1];
            accR[0][0] += fmaxf(c[0][nh][0] + bt0, 0.f) * wp0 + fmaxf(c[0][nh][1] + bt1, 0.f) * wp1;
            accR[0][1] += fmaxf(c[0][nh][2] + bt0, 0.f) * wp0 + fmaxf(c[0][nh][3] + bt1, 0.f) * wp1;
            accR[1][0] += fmaxf(c[1][nh][0] + bt0, 0.f) * wp0 + fmaxf(c[1][nh][1] + bt1, 0.f) * wp1;
            accR[1][1] += fmaxf(c[1][nh][2] + bt0, 0.f) * wp0 + fmaxf(c[1][nh][3] + bt1, 0.f) * wp1;
        }
    }
    // reduce over quad (lanes differing in bits 0,1 share a row)
#pragma unroll
    for (int o = 1; o <= 2; o <<= 1) {
        accR[0][0] += __shfl_xor_sync(0xffffffffu, accR[0][0], o);
        accR[0][1] += __shfl_xor_sync(0xffffffffu, accR[0][1], o);
        accR[1][0] += __shfl_xor_sync(0xffffffffu, accR[1][0], o);
        accR[1][1] += __shfl_xor_sync(0xffffffffu, accR[1][1], o);
    }
    if ((lane & 3) == 0) {
        int g = lane >> 2;
        float bp = sc[512 + s];
#pragma unroll
        for (int mt = 0; mt < 2; mt++)
#pragma unroll
            for (int hh = 0; hh < 2; hh++) {
                int row = mrow0 + mt * 16 + hh * 8 + g;
                size_t p = (size_t)blockIdx.x * 128 + (size_t)row;
                float tp = accR[mt][hh] + bp;
                float lg = (tp >= 0.f) ? -log1pf(expf(-tp)) : tp - log1pf(expf(tp));
                g_twlog[(size_t)s * (LL * LL) + p] = lg;
            }
    }
}

// ---------------- final LayerNorm (one row per block) ----------------
__global__ void lnf_kernel(const float* __restrict__ g, const float* __restrict__ b,
                           float* __restrict__ out) {
    int row = blockIdx.x, tid = threadIdx.x;
    float x = g_seq[row * DD + tid];
    float s = x, s2 = x * x;
#pragma unroll
    for (int o = 16; o; o >>= 1) {
        s  += __shfl_xor_sync(0xffffffffu, s, o);
        s2 += __shfl_xor_sync(0xffffffffu, s2, o);
    }
    __shared__ float sh[8];
    if ((tid & 31) == 0) { sh[tid >> 5] = s; sh[4 + (tid >> 5)] = s2; }
    __syncthreads();
    s  = sh[0] + sh[1] + sh[2] + sh[3];
    s2 = sh[4] + sh[5] + sh[6] + sh[7];
    float m = s * (1.0f / DD);
    float v = s2 * (1.0f / DD) - m * m;
    float r = rsqrtf(v + 1e-8f);
    out[row * DD + tid] = (x - m) * r * g[tid] + b[tid];
}

// ---- in-tile LayerNorm of As[32][128] (256 threads, 8 per row) ----
__device__ __forceinline__ void tile_ln(float* As, const float* __restrict__ g,
                                        const float* __restrict__ b, int tid,
                                        bool writeback, float* __restrict__ dst, int r0) {
    int r = tid >> 3, t8 = tid & 7;
    float s = 0.f, s2 = 0.f;
#pragma unroll
    for (int j = 0; j < 16; j++) {
        float v = As[r * 128 + t8 * 16 + j];
        s += v; s2 += v * v;
    }
#pragma unroll
    for (int o = 1; o <= 4; o <<= 1) {
        s  += __shfl_xor_sync(0xffffffffu, s, o);
        s2 += __shfl_xor_sync(0xffffffffu, s2, o);
    }
    float m = s * (1.0f / DD);
    float v = s2 * (1.0f / DD) - m * m;
    float rin = rsqrtf(v + 1e-8f);
#pragma unroll
    for (int j = 0; j < 16; j++) {
        int col = t8 * 16 + j;
        float val = (As[r * 128 + col] - m) * rin * g[col] + b[col];
        As[r * 128 + col] = val;
        if (writeback) dst[(r0 + r) * 128 + col] = val;
    }
    __syncthreads();
}

// ---------------- QKV with fused ln1 on z==0: grid (16, 4, 3) ----------------
__global__ void qkvln_kernel(const float* __restrict__ Wq, const float* __restrict__ bq,
                             const float* __restrict__ Wk, const float* __restrict__ bk,
                             const float* __restrict__ Wv, const float* __restrict__ bv,
                             const float* __restrict__ ln1g, const float* __restrict__ ln1b) {
    __shared__ float As[32 * 128];
    __shared__ float Ws[128 * 32];
    int z = blockIdx.z;
    const float* W    = (z == 0) ? Wq : (z == 1 ? Wk : Wv);
    const float* bias = (z == 0) ? bq : (z == 1 ? bk : bv);
    float* C          = (z == 0) ? g_qp : (z == 1 ? g_kp : g_vp);
    int r0 = blockIdx.x * 32, c0 = blockIdx.y * 32, tid = threadIdx.x;
    for (int i = tid; i < 32 * 128; i += 256) As[i] = g_seq[(r0 + (i >> 7)) * 128 + (i & 127)];
    for (int i = tid; i < 128 * 32; i += 256) Ws[i] = W[(i >> 5) * 128 + c0 + (i & 31)];
    __syncthreads();
    if (z == 0) tile_ln(As, ln1g, ln1b, tid, blockIdx.y == 0, g_Q, r0);
    int col = tid & 31, rg = tid >> 5;
    float acc[4] = {0, 0, 0, 0};
    for (int k = 0; k < 128; k++) {
        float w = Ws[k * 32 + col];
#pragma unroll
        for (int i = 0; i < 4; i++) acc[i] += As[(rg * 4 + i) * 128 + k] * w;
    }
    float b = bias[c0 + col];
#pragma unroll
    for (int i = 0; i < 4; i++) C[(r0 + rg * 4 + i) * 128 + c0 + col] = acc[i] + b;
}

// ---------------- FFN GEMM1 with fused ln2: relu(ln2(g_seq)@W1+b1) -> g_h ----
__global__ void gemm1_kernel(const float* __restrict__ W, const float* __restrict__ bias,
                             const float* __restrict__ ln2g, const float* __restrict__ ln2b) {
    __shared__ float As[32 * 128];
    __shared__ float Ws[128 * 32];
    int r0 = blockIdx.x * 32, c0 = blockIdx.y * 32, tid = threadIdx.x;
    for (int i = tid; i < 32 * 128; i += 256) As[i] = g_seq[(r0 + (i >> 7)) * 128 + (i & 127)];
    for (int i = tid; i < 128 * 32; i += 256) Ws[i] = W[(i >> 5) * 128 + c0 + (i & 31)];
    __syncthreads();
    tile_ln(As, ln2g, ln2b, tid, blockIdx.y == 0, g_x, r0);
    int col = tid & 31, rg = tid >> 5;
    float acc[4] = {0, 0, 0, 0};
    for (int k = 0; k < 128; k++) {
        float w = Ws[k * 32 + col];
#pragma unroll
        for (int i = 0; i < 4; i++) acc[i] += As[(rg * 4 + i) * 128 + k] * w;
    }
    float b = bias[c0 + col];
#pragma unroll
    for (int i = 0; i < 4; i++)
        g_h[(r0 + rg * 4 + i) * 128 + c0 + col] = fmaxf(acc[i] + b, 0.0f);
}

// ---------------- FFN GEMM2: (g_x + g_h@W2+b2)*keep -> g_seq ----------------
__global__ void gemm2_kernel(const float* __restrict__ W, const float* __restrict__ bias) {
    __shared__ float As[32 * 128];
    __shared__ float Ws[128 * 32];
    int r0 = blockIdx.x * 32, c0 = blockIdx.y * 32, tid = threadIdx.x;
    for (int i = tid; i < 32 * 128; i += 256) As[i] = g_h[(r0 + (i >> 7)) * 128 + (i & 127)];
    for (int i = tid; i < 128 * 32; i += 256) Ws[i] = W[(i >> 5) * 128 + c0 + (i & 31)];
    __syncthreads();
    int col = tid & 31, rg = tid >> 5;
    float acc[4] = {0, 0, 0, 0};
    for (int k = 0; k < 128; k++) {
        float w = Ws[k * 32 + col];
#pragma unroll
        for (int i = 0; i < 4; i++) acc[i] += As[(rg * 4 + i) * 128 + k] * w;
    }
    float b = bias[c0 + col];
#pragma unroll
    for (int i = 0; i < 4; i++) {
        int row = r0 + rg * 4 + i;
        g_seq[row * 128 + c0 + col] = (g_x[row * 128 + c0 + col] + acc[i] + b) * g_keep[row];
    }
}

// ---------------- attention v2: warp-per-q, grid (4, 32), 256 thr ------------
// smem: K and V staged [512][33] floats each
#define AT_SMEM (2 * 512 * 33 * 4)

__global__ void __launch_bounds__(256, 1)
attn_kernel(int s, float* __restrict__ wout) {
    extern __shared__ char smem[];
    float* ks = (float*)smem;
    float* vs = (float*)(smem + 512 * 33 * 4);
    const float* twlog = g_twlog + (size_t)s * (LL * LL);
    int h = blockIdx.x, q0 = blockIdx.y * 16, tid = threadIdx.x;
    int lane = tid & 31, w = tid >> 5;

    for (int i = tid; i < 512 * 32; i += 256) {
        int kk = i >> 5, d = i & 31;
        ks[kk * 33 + d] = g_kp[kk * 128 + h * 32 + d];
        vs[kk * 33 + d] = g_vp[kk * 128 + h * 32 + d];
    }
    __syncthreads();

    const float NEGV = -4294967295.0f;
    const float SCALE = 0.17677669529663689f;  // 1/sqrt(32)

    for (int qi = w; qi < 16; qi += 8) {
        int q = q0 + qi;
        float qd = g_qp[q * 128 + h * 32 + lane];
        bool padq = (g_keep[q] == 0.0f);
        float sv[16];
        float mx = -3.4e38f;
#pragma unroll
        for (int blk = 0; blk < 16; blk++) {
            int kk = blk * 32 + lane;
            float dot = 0.f;
#pragma unroll
            for (int d = 0; d < 32; d++) {
                float qv = __shfl_sync(0xffffffffu, qd, d);
                dot += qv * ks[kk * 33 + d];
            }
            float sva = (padq || kk > q) ? NEGV : (dot + twlog[q * 512 + kk]) * SCALE;
            sv[blk] = sva;
            mx = fmaxf(mx, sva);
        }
#pragma unroll
        for (int o = 16; o; o >>= 1) mx = fmaxf(mx, __shfl_xor_sync(0xffffffffu, mx, o));
        float sum = 0.f;
#pragma unroll
        for (int blk = 0; blk < 16; blk++) {
            float e = expf(sv[blk] - mx);
            sv[blk] = e;
            sum += e;
        }
#pragma unroll
        for (int o = 16; o; o >>= 1) sum += __shfl_xor_sync(0xffffffffu, sum, o);
        float inv = 1.0f / sum;
#pragma unroll
        for (int blk = 0; blk < 16; blk++) {
            float wv = sv[blk] * inv;
            sv[blk] = wv;
            wout[(size_t)h * 262144 + (size_t)q * 512 + blk * 32 + lane] = wv;
        }
        // V phase: lane owns output dim d = lane
        float acc = 0.f;
#pragma unroll
        for (int blk = 0; blk < 16; blk++) {
#pragma unroll
            for (int src = 0; src < 32; src++) {
                float wv = __shfl_sync(0xffffffffu, sv[blk], src);
                acc += wv * vs[(blk * 32 + src) * 33 + lane];
            }
        }
        g_seq[q * 128 + h * 32 + lane] = g_Q[q * 128 + h * 32 + lane] + acc;
    }
}

// ---------------- launch ----------------
extern "C" void kernel_launch(void* const* d_in, const int* in_sizes, int n_in,
                              void* d_out, int out_size) {
    const int*   logs = (const int*)d_in[0];
    const float* seqs = (const float*)d_in[1];
    const float* tmk  = (const float*)d_in[2];
    const float* Wq   = (const float*)d_in[3];
    const float* bq   = (const float*)d_in[4];
    const float* Wk   = (const float*)d_in[5];
    const float* bk   = (const float*)d_in[6];
    const float* Wv   = (const float*)d_in[7];
    const float* bv   = (const float*)d_in[8];
    const float* Wt   = (const float*)d_in[9];
    const float* bt   = (const float*)d_in[10];
    const float* Wtp  = (const float*)d_in[11];
    const float* btp  = (const float*)d_in[12];
    const float* ln1g = (const float*)d_in[13];
    const float* ln1b = (const float*)d_in[14];
    const float* ln2g = (const float*)d_in[15];
    const float* ln2b = (const float*)d_in[16];
    const float* W1   = (const float*)d_in[17];
    const float* b1   = (const float*)d_in[18];
    const float* W2   = (const float*)d_in[19];
    const float* b2   = (const float*)d_in[20];
    const float* lnfg = (const float*)d_in[21];
    const float* lnfb = (const float*)d_in[22];
    float* out = (float*)d_out;

    cudaFuncSetAttribute(twbias_kernel, cudaFuncAttributeMaxDynamicSharedMemorySize, TW_SMEM);
    cudaFuncSetAttribute(attn_kernel, cudaFuncAttributeMaxDynamicSharedMemorySize, AT_SMEM);

    prep_keep_kernel<<<1, 512>>>(logs);
    prep_seq_kernel<<<256, 256>>>(logs, seqs);
    bimg_kernel<<<128, 256>>>(Wt);
    twbias_kernel<<<2048, 256, TW_SMEM>>>(tmk, bt, Wtp, btp);

    for (int i = 0; i < 2; i++) {
        const int wo = i * 16384, bo = i * 128;
        qkvln_kernel<<<dim3(16, 4, 3), 256>>>(Wq + wo, bq + bo, Wk + wo, bk + bo,
                                              Wv + wo, bv + bo, ln1g + bo, ln1b + bo);
        attn_kernel<<<dim3(4, 32), 256, AT_SMEM>>>(i, out + 65536 + (size_t)i * 1048576);
        gemm1_kernel<<<dim3(16, 4), 256>>>(W1 + wo, b1 + bo, ln2g + bo, ln2b + bo);
        gemm2_kernel<<<dim3(16, 4), 256>>>(W2 + wo, b2 + bo);
    }
    lnf_kernel<<<512, 128>>>(lnfg, lnfb, out);
}

// round 7
// speedup vs baseline: 1.4886x; 1.3194x over previous
#include <cuda_runtime.h>
#include <cuda_bf16.h>
#include <cstdint>

#define LL 512
#define DD 128
#define NCTA 128

// ---------------- scratch globals ----------------
__device__ float g_keep[LL];
__device__ float g_seq[LL * DD];
__device__ float g_Q[LL * DD];
__device__ float g_qp[LL * DD];
__device__ float g_kp[LL * DD];
__device__ float g_vp[LL * DD];
__device__ float g_x[LL * DD];
__device__ float g_h[LL * DD];
__device__ float g_twlog[2 * LL * LL];
__device__ __nv_bfloat16 g_Bimg[2 * 128 * 128];  // [s][n][k] = Wt[s][k][n]

__device__ unsigned g_bar_count;
__device__ volatile unsigned g_bar_gen;

__device__ __forceinline__ void grid_barrier() {
    __syncthreads();
    if (threadIdx.x == 0) {
        __threadfence();                       // flush + order my writes
        unsigned gen = g_bar_gen;
        if (atomicAdd(&g_bar_count, 1u) == NCTA - 1) {
            atomicExch(&g_bar_count, 0u);      // L2-level reset
            __threadfence();
            g_bar_gen = gen + 1u;              // volatile store (L2)
        } else {
            while (g_bar_gen == gen) __nanosleep(64);
        }
        __threadfence();                       // invalidate stale L1 before reads
    }
    __syncthreads();
}

__device__ __forceinline__ uint32_t smem_to_u32(const void* p) {
    uint32_t a;
    asm("{ .reg .u64 t; cvta.to.shared.u64 t, %1; cvt.u32.u64 %0, t; }" : "=r"(a) : "l"(p));
    return a;
}
__device__ __forceinline__ void ldmatrix_x4(uint32_t* r, uint32_t addr) {
    asm volatile("ldmatrix.sync.aligned.m8n8.x4.shared.b16 {%0,%1,%2,%3}, [%4];"
                 : "=r"(r[0]), "=r"(r[1]), "=r"(r[2]), "=r"(r[3]) : "r"(addr));
}
__device__ __forceinline__ void mma16816(float* c, const uint32_t* a, uint32_t b0, uint32_t b1) {
    asm volatile(
        "mma.sync.aligned.m16n8k16.row.col.f32.bf16.bf16.f32 "
        "{%0,%1,%2,%3}, {%4,%5,%6,%7}, {%8,%9}, {%0,%1,%2,%3};"
        : "+f"(c[0]), "+f"(c[1]), "+f"(c[2]), "+f"(c[3])
        : "r"(a[0]), "r"(a[1]), "r"(a[2]), "r"(a[3]), "r"(b0), "r"(b1));
}

// ---------------- prep: keep + masked seqs + B images, one kernel -----------
__global__ void prep_all_kernel(const int* __restrict__ logs, const float* __restrict__ seqs,
                                const float* __restrict__ Wt) {
    int i = blockIdx.x * 256 + threadIdx.x;  // 65536
    if (i < LL) g_keep[i] = (logs[i] == 0) ? 0.0f : 1.0f;
    int row = i >> 7;
    float k = (logs[row] == 0) ? 0.0f : 1.0f;
    g_seq[i] = seqs[i] * k;
    if (i < 32768) {
        int s = i >> 14, e = i & 16383;
        int n = e >> 7, kk = e & 127;
        g_Bimg[i] = __float2bfloat16(Wt[s * 16384 + kk * 128 + n]);
    }
}

// ---------------- big fused time-bias kernel (HMMA mma.sync) ----------------
#define TW_SA   0
#define TW_SB   34816
#define TW_SSC  (TW_SB + 2 * 34816)      // 104448
#define TW_SMEM (TW_SSC + 2064)          // 106512

__global__ void __launch_bounds__(256, 2)
twbias_kernel(const float* __restrict__ T, const float* __restrict__ bt,
              const float* __restrict__ Wtp, const float* __restrict__ btp) {
    extern __shared__ char smem[];
    uint32_t sb = smem_to_u32(smem);
    int tid = threadIdx.x;
    float* sc = (float*)(smem + TW_SSC);

    {   // stage B images (padded rows, 272B stride)
        const uint4* src = (const uint4*)g_Bimg;
        for (int i = tid; i < 4096; i += 256) {
            int e = i * 8;
            int s = e >> 14, n = (e >> 7) & 127, k = e & 127;
            *(uint4*)(smem + TW_SB + s * 34816 + n * 272 + k * 2) = src[i];
        }
    }
    if (tid < 128) {
        sc[tid]       = bt[tid];
        sc[128 + tid] = bt[128 + tid];
        sc[256 + tid] = Wtp[tid];
        sc[384 + tid] = Wtp[128 + tid];
    }
    if (tid == 0) { sc[512] = btp[0]; sc[513] = btp[1]; }

    {   // A tile: 128 rows x 128 fp32 -> bf16, stride 272B
        size_t r0 = (size_t)blockIdx.x * 128;
        const float4* Tb = (const float4*)(T + r0 * 128);
#pragma unroll
        for (int i = 0; i < 16; i++) {
            int c = tid + 256 * i;
            int r = c >> 5, kc = (c & 31) << 2;
            float4 a = Tb[c];
            __nv_bfloat162 lo = __floats2bfloat162_rn(a.x, a.y);
            __nv_bfloat162 hi = __floats2bfloat162_rn(a.z, a.w);
            uint2 u;
            u.x = *reinterpret_cast<uint32_t*>(&lo);
            u.y = *reinterpret_cast<uint32_t*>(&hi);
            *(uint2*)(smem + TW_SA + r * 272 + kc * 2) = u;
        }
    }
    __syncthreads();

    int lane = tid & 31, w = tid >> 5;
    int s = w >> 2, mrow0 = (w & 3) * 32;
    int l8 = lane & 7, gq = lane >> 3;
    int arow = (gq & 1) * 8 + l8;
    int akoff = (gq >> 1) * 8;

    uint32_t a[2][8][4];
#pragma unroll
    for (int mt = 0; mt < 2; mt++)
#pragma unroll
        for (int kt = 0; kt < 8; kt++) {
            uint32_t addr = sb + TW_SA + (uint32_t)(mrow0 + mt * 16 + arow) * 272
                          + (uint32_t)(kt * 16 + akoff) * 2;
            ldmatrix_x4(a[mt][kt], addr);
        }

    int bntl = gq >> 1;
    int bkoff = (gq & 1) * 8;
    uint32_t b_base = sb + TW_SB + (uint32_t)s * 34816;
    int qd = lane & 3;

    float accR[2][2] = {{0.f, 0.f}, {0.f, 0.f}};
#pragma unroll
    for (int ntp = 0; ntp < 8; ntp++) {
        float c[2][2][4] = {};
        uint32_t brow = (uint32_t)(ntp * 16 + bntl * 8 + l8) * 272;
        uint32_t bb[2][4];
        ldmatrix_x4(bb[0], b_base + brow + (uint32_t)bkoff * 2);
#pragma unroll
        for (int kt = 0; kt < 8; kt++) {
            if (kt < 7)
                ldmatrix_x4(bb[(kt + 1) & 1],
                            b_base + brow + (uint32_t)((kt + 1) * 16 + bkoff) * 2);
            const uint32_t* b = bb[kt & 1];
            mma16816(c[0][0], a[0][kt], b[0], b[1]);
            mma16816(c[0][1], a[0][kt], b[2], b[3]);
            mma16816(c[1][0], a[1][kt], b[0], b[1]);
            mma16816(c[1][1], a[1][kt], b[2], b[3]);
        }
#pragma unroll
        for (int nh = 0; nh < 2; nh++) {
            int n0 = (ntp * 2 + nh) * 8 + 2 * qd;
            float bt0 = sc[s * 128 + n0],       bt1 = sc[s * 128 + n0 + 1];
            float wp0 = sc[256 + s * 128 + n0], wp1 = sc[256 + s * 128 + n0 + 1];
            accR[0][0] += fmaxf(c[0][nh][0] + bt0, 0.f) * wp0 + fmaxf(c[0][nh][1] + bt1, 0.f) * wp1;
            accR[0][1] += fmaxf(c[0][nh][2] + bt0, 0.f) * wp0 + fmaxf(c[0][nh][3] + bt1, 0.f) * wp1;
            accR[1][0] += fmaxf(c[1][nh][0] + bt0, 0.f) * wp0 + fmaxf(c[1][nh][1] + bt1, 0.f) * wp1;
            accR[1][1] += fmaxf(c[1][nh][2] + bt0, 0.f) * wp0 + fmaxf(c[1][nh][3] + bt1, 0.f) * wp1;
        }
    }
#pragma unroll
    for (int o = 1; o <= 2; o <<= 1) {
        accR[0][0] += __shfl_xor_sync(0xffffffffu, accR[0][0], o);
        accR[0][1] += __shfl_xor_sync(0xffffffffu, accR[0][1], o);
        accR[1][0] += __shfl_xor_sync(0xffffffffu, accR[1][0], o);
        accR[1][1] += __shfl_xor_sync(0xffffffffu, accR[1][1], o);
    }
    if ((lane & 3) == 0) {
        int g = lane >> 2;
        float bp = sc[512 + s];
#pragma unroll
        for (int mt = 0; mt < 2; mt++)
#pragma unroll
            for (int hh = 0; hh < 2; hh++) {
                int row = mrow0 + mt * 16 + hh * 8 + g;
                size_t p = (size_t)blockIdx.x * 128 + (size_t)row;
                float tp = accR[mt][hh] + bp;
                float lg = (tp >= 0.f) ? -log1pf(expf(-tp)) : tp - log1pf(expf(tp));
                g_twlog[(size_t)s * (LL * LL) + p] = lg;
            }
    }
}

// ---- in-tile LayerNorm of As[16][128] (256 thr, 16 per row) ----
__device__ __forceinline__ void tile_ln16(float* As, const float* __restrict__ g,
                                          const float* __restrict__ b, int tid,
                                          bool wb, float* __restrict__ dst, int r0) {
    int r = tid >> 4, t16 = tid & 15;
    float s = 0.f, s2 = 0.f;
#pragma unroll
    for (int j = 0; j < 8; j++) {
        float v = As[r * 128 + t16 * 8 + j];
        s += v; s2 += v * v;
    }
#pragma unroll
    for (int o = 1; o <= 8; o <<= 1) {
        s  += __shfl_xor_sync(0xffffffffu, s, o);
        s2 += __shfl_xor_sync(0xffffffffu, s2, o);
    }
    float m = s * (1.0f / DD);
    float var = s2 * (1.0f / DD) - m * m;
    float rin = rsqrtf(var + 1e-8f);
#pragma unroll
    for (int j = 0; j < 8; j++) {
        int c = t16 * 8 + j;
        float val = (As[r * 128 + c] - m) * rin * g[c] + b[c];
        As[r * 128 + c] = val;
        if (wb) dst[(r0 + r) * 128 + c] = val;
    }
    __syncthreads();
}

// ---------------- persistent fused tail kernel: 128 CTAs x 256 thr ----------
#define TAIL_SMEM (2 * 512 * 33 * 4)    // attn K+V staging (GEMM phases use a prefix)

__global__ void __launch_bounds__(256)
tail_kernel(const float* __restrict__ Wq, const float* __restrict__ bq,
            const float* __restrict__ Wk, const float* __restrict__ bk,
            const float* __restrict__ Wv, const float* __restrict__ bv,
            const float* __restrict__ ln1g, const float* __restrict__ ln1b,
            const float* __restrict__ ln2g, const float* __restrict__ ln2b,
            const float* __restrict__ W1, const float* __restrict__ b1,
            const float* __restrict__ W2, const float* __restrict__ b2,
            const float* __restrict__ lnfg, const float* __restrict__ lnfb,
            float* __restrict__ out) {
    extern __shared__ float fsm[];
    float* As = fsm;                 // 16*128
    float* Ws = fsm + 16 * 128;      // 128*32
    int cta = blockIdx.x, tid = threadIdx.x;
    int lane = tid & 31, w = tid >> 5;
    const float NEGV = -4294967295.0f;
    const float SCALE = 0.17677669529663689f;  // 1/sqrt(32)

    for (int i = 0; i < 2; i++) {
        const int wo = i * 16384, bo = i * 128;
        int r0 = (cta >> 2) * 16, c0 = (cta & 3) * 32;

        // ---- phase A: ln1 (z==0) + Q/K/V projections, 16x32 tiles ----
#pragma unroll 1
        for (int z = 0; z < 3; z++) {
            const float* W    = (z == 0) ? Wq + wo : (z == 1) ? Wk + wo : Wv + wo;
            const float* bias = (z == 0) ? bq + bo : (z == 1) ? bk + bo : bv + bo;
            float* C          = (z == 0) ? g_qp : (z == 1) ? g_kp : g_vp;
            for (int t = tid; t < 16 * 128; t += 256)
                As[t] = g_seq[(r0 + (t >> 7)) * 128 + (t & 127)];
            for (int t = tid; t < 128 * 32; t += 256)
                Ws[t] = W[(t >> 5) * 128 + c0 + (t & 31)];
            __syncthreads();
            if (z == 0) tile_ln16(As, ln1g + bo, ln1b + bo, tid, c0 == 0, g_Q, r0);
            float a0 = 0.f, a1 = 0.f;
            for (int k = 0; k < 128; k++) {
                float wv = Ws[k * 32 + lane];
                a0 += As[(w * 2) * 128 + k] * wv;
                a1 += As[(w * 2 + 1) * 128 + k] * wv;
            }
            float bb = bias[c0 + lane];
            C[(r0 + w * 2) * 128 + c0 + lane]     = a0 + bb;
            C[(r0 + w * 2 + 1) * 128 + c0 + lane] = a1 + bb;
            __syncthreads();
        }
        grid_barrier();

        // ---- phase B: attention (warp-per-q), CTA = (h, q-block of 16) ----
        {
            float* ks = fsm;
            float* vs = fsm + 512 * 33;
            int h = cta >> 5, q0 = (cta & 31) * 16;
            for (int t = tid; t < 512 * 32; t += 256) {
                int kk = t >> 5, d = t & 31;
                ks[kk * 33 + d] = g_kp[kk * 128 + h * 32 + d];
                vs[kk * 33 + d] = g_vp[kk * 128 + h * 32 + d];
            }
            __syncthreads();
            float* wout = out + 65536 + (size_t)i * 1048576;
            for (int qi = w; qi < 16; qi += 8) {
                int q = q0 + qi;
                float qreg[32];
                const float4* q4 = (const float4*)(g_qp + q * 128 + h * 32);
#pragma unroll
                for (int j = 0; j < 8; j++) {
                    float4 t4 = q4[j];
                    qreg[j * 4]     = t4.x; qreg[j * 4 + 1] = t4.y;
                    qreg[j * 4 + 2] = t4.z; qreg[j * 4 + 3] = t4.w;
                }
                bool padq = (g_keep[q] == 0.0f);
                const float* tw = g_twlog + (size_t)i * (LL * LL) + (size_t)q * 512;
                float sv[16];
                float mx = -3.4e38f;
#pragma unroll
                for (int blk = 0; blk < 16; blk++) {
                    int kk = blk * 32 + lane;
                    float dot = 0.f;
#pragma unroll
                    for (int d = 0; d < 32; d++) dot += qreg[d] * ks[kk * 33 + d];
                    float sva = (padq || kk > q) ? NEGV : (dot + tw[kk]) * SCALE;
                    sv[blk] = sva;
                    mx = fmaxf(mx, sva);
                }
#pragma unroll
                for (int o = 16; o; o >>= 1) mx = fmaxf(mx, __shfl_xor_sync(0xffffffffu, mx, o));
                float sum = 0.f;
#pragma unroll
                for (int blk = 0; blk < 16; blk++) {
                    float e = expf(sv[blk] - mx);
                    sv[blk] = e;
                    sum += e;
                }
#pragma unroll
                for (int o = 16; o; o >>= 1) sum += __shfl_xor_sync(0xffffffffu, sum, o);
                float inv = 1.0f / sum;
#pragma unroll
                for (int blk = 0; blk < 16; blk++) {
                    float wv = sv[blk] * inv;
                    sv[blk] = wv;
                    wout[(size_t)h * 262144 + (size_t)q * 512 + blk * 32 + lane] = wv;
                }
                float acc = 0.f;
#pragma unroll
                for (int blk = 0; blk < 16; blk++) {
#pragma unroll
                    for (int src = 0; src < 32; src++) {
                        float wv = __shfl_sync(0xffffffffu, sv[blk], src);
                        acc += wv * vs[(blk * 32 + src) * 33 + lane];
                    }
                }
                g_seq[q * 128 + h * 32 + lane] = g_Q[q * 128 + h * 32 + lane] + acc;
            }
            __syncthreads();
        }
        grid_barrier();

        // ---- phase C: ln2 + FFN1: relu(ln2(g_seq)@W1+b1) -> g_h ----
        {
            for (int t = tid; t < 16 * 128; t += 256)
                As[t] = g_seq[(r0 + (t >> 7)) * 128 + (t & 127)];
            for (int t = tid; t < 128 * 32; t += 256)
                Ws[t] = W1[wo + (t >> 5) * 128 + c0 + (t & 31)];
            __syncthreads();
            tile_ln16(As, ln2g + bo, ln2b + bo, tid, c0 == 0, g_x, r0);
            float a0 = 0.f, a1 = 0.f;
            for (int k = 0; k < 128; k++) {
                float wv = Ws[k * 32 + lane];
                a0 += As[(w * 2) * 128 + k] * wv;
                a1 += As[(w * 2 + 1) * 128 + k] * wv;
            }
            float bb = b1[bo + c0 + lane];
            g_h[(r0 + w * 2) * 128 + c0 + lane]     = fmaxf(a0 + bb, 0.f);
            g_h[(r0 + w * 2 + 1) * 128 + c0 + lane] = fmaxf(a1 + bb, 0.f);
            __syncthreads();
        }
        grid_barrier();

        // ---- phase D: FFN2: (g_x + g_h@W2+b2)*keep -> g_seq ----
        {
            for (int t = tid; t < 16 * 128; t += 256)
                As[t] = g_h[(r0 + (t >> 7)) * 128 + (t & 127)];
            for (int t = tid; t < 128 * 32; t += 256)
                Ws[t] = W2[wo + (t >> 5) * 128 + c0 + (t & 31)];
            __syncthreads();
            float a0 = 0.f, a1 = 0.f;
            for (int k = 0; k < 128; k++) {
                float wv = Ws[k * 32 + lane];
                a0 += As[(w * 2) * 128 + k] * wv;
                a1 += As[(w * 2 + 1) * 128 + k] * wv;
            }
            float bb = b2[bo + c0 + lane];
            int row0 = r0 + w * 2, row1 = row0 + 1;
            g_seq[row0 * 128 + c0 + lane] =
                (g_x[row0 * 128 + c0 + lane] + a0 + bb) * g_keep[row0];
            g_seq[row1 * 128 + c0 + lane] =
                (g_x[row1 * 128 + c0 + lane] + a1 + bb) * g_keep[row1];
            __syncthreads();
        }
        grid_barrier();
    }

    // ---- final LayerNorm: warp-per-row ----
    if (w < 4) {
        int row = cta * 4 + w;
        const float4* sr = (const float4*)(g_seq + row * 128);
        float4 xv = sr[lane];
        float s = xv.x + xv.y + xv.z + xv.w;
        float s2 = xv.x * xv.x + xv.y * xv.y + xv.z * xv.z + xv.w * xv.w;
#pragma unroll
        for (int o = 16; o; o >>= 1) {
            s  += __shfl_xor_sync(0xffffffffu, s, o);
            s2 += __shfl_xor_sync(0xffffffffu, s2, o);
        }
        float m = s * (1.0f / DD);
        float var = s2 * (1.0f / DD) - m * m;
        float rin = rsqrtf(var + 1e-8f);
        float4 gv = ((const float4*)lnfg)[lane];
        float4 bv4 = ((const float4*)lnfb)[lane];
        float4 o4;
        o4.x = (xv.x - m) * rin * gv.x + bv4.x;
        o4.y = (xv.y - m) * rin * gv.y + bv4.y;
        o4.z = (xv.z - m) * rin * gv.z + bv4.z;
        o4.w = (xv.w - m) * rin * gv.w + bv4.w;
        ((float4*)(out + row * 128))[lane] = o4;
    }
}

// ---------------- launch ----------------
extern "C" void kernel_launch(void* const* d_in, const int* in_sizes, int n_in,
                              void* d_out, int out_size) {
    const int*   logs = (const int*)d_in[0];
    const float* seqs = (const float*)d_in[1];
    const float* tmk  = (const float*)d_in[2];
    const float* Wq   = (const float*)d_in[3];
    const float* bq   = (const float*)d_in[4];
    const float* Wk   = (const float*)d_in[5];
    const float* bk   = (const float*)d_in[6];
    const float* Wv   = (const float*)d_in[7];
    const float* bv   = (const float*)d_in[8];
    const float* Wt   = (const float*)d_in[9];
    const float* bt   = (const float*)d_in[10];
    const float* Wtp  = (const float*)d_in[11];
    const float* btp  = (const float*)d_in[12];
    const float* ln1g = (const float*)d_in[13];
    const float* ln1b = (const float*)d_in[14];
    const float* ln2g = (const float*)d_in[15];
    const float* ln2b = (const float*)d_in[16];
    const float* W1   = (const float*)d_in[17];
    const float* b1   = (const float*)d_in[18];
    const float* W2   = (const float*)d_in[19];
    const float* b2   = (const float*)d_in[20];
    const float* lnfg = (const float*)d_in[21];
    const float* lnfb = (const float*)d_in[22];
    float* out = (float*)d_out;

    cudaFuncSetAttribute(twbias_kernel, cudaFuncAttributeMaxDynamicSharedMemorySize, TW_SMEM);
    cudaFuncSetAttribute(tail_kernel, cudaFuncAttributeMaxDynamicSharedMemorySize, TAIL_SMEM);

    prep_all_kernel<<<256, 256>>>(logs, seqs, Wt);
    twbias_kernel<<<2048, 256, TW_SMEM>>>(tmk, bt, Wtp, btp);
    tail_kernel<<<NCTA, 256, TAIL_SMEM>>>(Wq, bq, Wk, bk, Wv, bv, ln1g, ln1b,
                                          ln2g, ln2b, W1, b1, W2, b2, lnfg, lnfb, out);
}